// round 1
// baseline (speedup 1.0000x reference)
#include <cuda_runtime.h>

#define BB 128
#define NN 100
#define EE 3200
#define EDD 8
#define NT 512

struct Args {
    const float* nodes;   // [B*N] float (values 0..4)
    const int*   ei;      // [B,2,E]
    const float* ea;      // [B*E,8]
    const int*   agent;   // [B]
    const float* emb;     // [5,4]
    const float *W1,*b1,*W2,*b2,*W3,*b3,*lng,*lnb;
    const float *g1Wq,*g1bq,*g1Wk,*g1bk,*g1Wv,*g1bv,*g1We,*g1Ws,*g1bs;
    const float *g2Wq,*g2bq,*g2Wk,*g2bk,*g2Wv,*g2bv,*g2We,*g2Ws,*g2bs;
    float* out;           // [B,32]
};

// per-edge MLP output scratch (block-private slices; written+read within one CTA
// across a __syncthreads, which orders global accesses at block scope)
__device__ float g_hbuf[(size_t)BB * EE * 16];

struct SM {
    float z[NN * 17];                 // node embeddings (padded stride 17)
    float q[NN * 65], k[NN * 65], v[NN * 65];   // g1 qkv (padded stride 65)
    float root1[NN * 16];
    float denom1[NN * 4];
    float acc1[NN * 64];
    float a[NN * 17];                 // g1 output (padded)
    float expl[EE * 4];               // per-edge per-head exp(logit)
    // weights
    float W1[192], b1[16], W2[256], b2[16], W3[256], b3[16], lng[16], lnb[16], emb[20];
    float g1Wq[1024], g1bq[64], g1Wk[1024], g1bk[64], g1Wv[1024], g1bv[64];
    float g1We[512], g1Ws[256], g1bs[16];
    // g2 (agent-only) small state
    float qa[128], roota[32], denom2[4], acc2[128];
    // CSR by dst
    int csr[EE];          // packed (src<<16)|e
    int rowptr[NN + 1];
    int cursor[NN];
    int deg[NN];
    int etype[NN];
    int agent;
};
static_assert(sizeof(SM) <= 232448, "smem over limit");

__device__ __forceinline__ void cpf(float* d, const float* s, int n, int tid) {
    for (int i = tid; i < n; i += NT) d[i] = s[i];
}

__device__ __forceinline__ void ln16(float* h, const float* g, const float* bb) {
    float m = 0.f;
#pragma unroll
    for (int i = 0; i < 16; i++) m += h[i];
    m *= (1.f / 16.f);
    float var = 0.f;
#pragma unroll
    for (int i = 0; i < 16; i++) { float d = h[i] - m; var += d * d; }
    var *= (1.f / 16.f);
    float inv = rsqrtf(var + 1e-5f);
#pragma unroll
    for (int i = 0; i < 16; i++) h[i] = (h[i] - m) * inv * g[i] + bb[i];
}

__global__ void __launch_bounds__(NT, 1) gnn_kernel(Args A) {
    extern __shared__ unsigned char smraw[];
    SM* s = reinterpret_cast<SM*>(smraw);
    const int b = blockIdx.x;
    const int tid = threadIdx.x;
    const int* ei = A.ei + b * 2 * EE;
    const float* eag = A.ea + (size_t)b * EE * EDD;

    // ---- S0: load weights, node types, zero accumulators ----
    cpf(s->W1, A.W1, 192, tid);  cpf(s->b1, A.b1, 16, tid);
    cpf(s->W2, A.W2, 256, tid);  cpf(s->b2, A.b2, 16, tid);
    cpf(s->W3, A.W3, 256, tid);  cpf(s->b3, A.b3, 16, tid);
    cpf(s->lng, A.lng, 16, tid); cpf(s->lnb, A.lnb, 16, tid);
    cpf(s->emb, A.emb, 20, tid);
    cpf(s->g1Wq, A.g1Wq, 1024, tid); cpf(s->g1bq, A.g1bq, 64, tid);
    cpf(s->g1Wk, A.g1Wk, 1024, tid); cpf(s->g1bk, A.g1bk, 64, tid);
    cpf(s->g1Wv, A.g1Wv, 1024, tid); cpf(s->g1bv, A.g1bv, 64, tid);
    cpf(s->g1We, A.g1We, 512, tid);
    cpf(s->g1Ws, A.g1Ws, 256, tid); cpf(s->g1bs, A.g1bs, 16, tid);
    for (int i = tid; i < NN; i += NT) {
        s->etype[i] = (int)A.nodes[b * NN + i];
        s->deg[i] = 0;
    }
    for (int i = tid; i < 4; i += NT) s->denom2[i] = 0.f;
    for (int i = tid; i < 128; i += NT) s->acc2[i] = 0.f;
    if (tid == 0) s->agent = A.agent[b];
    __syncthreads();

    // ---- S0b: dst degree histogram ----
    for (int e = tid; e < EE; e += NT) atomicAdd(&s->deg[ei[EE + e]], 1);
    __syncthreads();

    // ---- S0c: prefix sum (serial over 100; trivial) ----
    if (tid == 0) {
        int run = 0;
        for (int n = 0; n < NN; n++) {
            s->rowptr[n] = run; s->cursor[n] = run; run += s->deg[n];
        }
        s->rowptr[NN] = run;
    }
    __syncthreads();

    // ---- S1a: CSR scatter + per-edge MLP -> g_hbuf ----
    for (int e = tid; e < EE; e += NT) {
        const int src = ei[e], dst = ei[EE + e];
        const int pos = atomicAdd(&s->cursor[dst], 1);
        s->csr[pos] = (src << 16) | e;

        float x0[12];
        {
            const int t = s->etype[src];
#pragma unroll
            for (int j = 0; j < 4; j++) x0[j] = s->emb[t * 4 + j];
            const float4 e0 = *(const float4*)(eag + (size_t)e * 8);
            const float4 e1 = *(const float4*)(eag + (size_t)e * 8 + 4);
            x0[4] = e0.x; x0[5] = e0.y; x0[6] = e0.z; x0[7] = e0.w;
            x0[8] = e1.x; x0[9] = e1.y; x0[10] = e1.z; x0[11] = e1.w;
        }
        float hA[16], hB[16];
#pragma unroll
        for (int o = 0; o < 16; o++) {
            float acc = s->b1[o];
#pragma unroll
            for (int j = 0; j < 12; j++) acc += s->W1[o * 12 + j] * x0[j];
            hA[o] = fmaxf(acc, 0.f);
        }
        ln16(hA, s->lng, s->lnb);
#pragma unroll
        for (int o = 0; o < 16; o++) {
            float acc = s->b2[o];
#pragma unroll
            for (int j = 0; j < 16; j++) acc += s->W2[o * 16 + j] * hA[j];
            hB[o] = fmaxf(acc, 0.f);
        }
        ln16(hB, s->lng, s->lnb);
#pragma unroll
        for (int o = 0; o < 16; o++) {
            float acc = s->b3[o];
#pragma unroll
            for (int j = 0; j < 16; j++) acc += s->W3[o * 16 + j] * hB[j];
            hA[o] = fmaxf(acc, 0.f);
        }
        ln16(hA, s->lng, s->lnb);

        float4* hp = (float4*)&g_hbuf[((size_t)b * EE + e) * 16];
        hp[0] = make_float4(hA[0], hA[1], hA[2], hA[3]);
        hp[1] = make_float4(hA[4], hA[5], hA[6], hA[7]);
        hp[2] = make_float4(hA[8], hA[9], hA[10], hA[11]);
        hp[3] = make_float4(hA[12], hA[13], hA[14], hA[15]);
    }
    __syncthreads();

    // ---- S1b: z = segment_sum(h, dst) via CSR gather (no atomics) ----
    for (int idx = tid; idx < NN * 16; idx += NT) {
        const int n = idx >> 4, c = idx & 15;
        const int p0 = s->rowptr[n], p1 = s->rowptr[n + 1];
        float acc = 0.f;
        for (int p = p0; p < p1; p++) {
            const int e = s->csr[p] & 0xFFFF;
            acc += g_hbuf[((size_t)b * EE + e) * 16 + c];
        }
        s->z[n * 17 + c] = acc;
    }
    __syncthreads();

    // ---- S2: g1 q,k,v and root ----
    for (int idx = tid; idx < NN * 64; idx += NT) {
        const int n = idx >> 6, u = idx & 63;
        const float* zr = &s->z[n * 17];
        float aq = s->g1bq[u], ak = s->g1bk[u], av = s->g1bv[u];
#pragma unroll
        for (int j = 0; j < 16; j++) {
            const float zj = zr[j];
            aq += s->g1Wq[u * 16 + j] * zj;
            ak += s->g1Wk[u * 16 + j] * zj;
            av += s->g1Wv[u * 16 + j] * zj;
        }
        s->q[n * 65 + u] = aq; s->k[n * 65 + u] = ak; s->v[n * 65 + u] = av;
    }
    for (int idx = tid; idx < NN * 16; idx += NT) {
        const int n = idx >> 4, o = idx & 15;
        float ac = s->g1bs[o];
#pragma unroll
        for (int j = 0; j < 16; j++) ac += s->g1Ws[o * 16 + j] * s->z[n * 17 + j];
        s->root1[idx] = ac;
    }
    __syncthreads();

    // ---- S3a: per-edge logits -> expl ----
    for (int e = tid; e < EE; e += NT) {
        const int src = ei[e], dst = ei[EE + e];
        float ear[8];
        {
            const float4 e0 = *(const float4*)(eag + (size_t)e * 8);
            const float4 e1 = *(const float4*)(eag + (size_t)e * 8 + 4);
            ear[0] = e0.x; ear[1] = e0.y; ear[2] = e0.z; ear[3] = e0.w;
            ear[4] = e1.x; ear[5] = e1.y; ear[6] = e1.z; ear[7] = e1.w;
        }
        const float* qd = &s->q[dst * 65];
        const float* ks = &s->k[src * 65];
#pragma unroll
        for (int hh = 0; hh < 4; hh++) {
            float lg = 0.f;
#pragma unroll
            for (int c = 0; c < 16; c++) {
                const int u = hh * 16 + c;
                float ev = 0.f;
#pragma unroll
                for (int j = 0; j < 8; j++) ev += s->g1We[u * 8 + j] * ear[j];
                lg += qd[u] * (ks[u] + ev);
            }
            s->expl[e * 4 + hh] = __expf(lg * 0.25f);
        }
    }
    __syncthreads();

    // ---- S3b: message gather + softmax denom (no atomics) ----
    for (int idx = tid; idx < NN * 64; idx += NT) {
        const int n = idx >> 6, u = idx & 63, hh = u >> 4;
        const int p0 = s->rowptr[n], p1 = s->rowptr[n + 1];
        float acc = 0.f;
        for (int p = p0; p < p1; p++) {
            const int pk = s->csr[p];
            const int e = pk & 0xFFFF, src = pk >> 16;
            const float* ear = eag + (size_t)e * 8;
            float ev = 0.f;
#pragma unroll
            for (int j = 0; j < 8; j++) ev += s->g1We[u * 8 + j] * ear[j];
            acc += s->expl[e * 4 + hh] * (s->v[src * 65 + u] + ev);
        }
        s->acc1[n * 64 + u] = acc;
    }
    for (int idx = tid; idx < NN * 4; idx += NT) {
        const int n = idx >> 2, hh = idx & 3;
        const int p0 = s->rowptr[n], p1 = s->rowptr[n + 1];
        float d = 0.f;
        for (int p = p0; p < p1; p++) d += s->expl[(s->csr[p] & 0xFFFF) * 4 + hh];
        s->denom1[idx] = d;
    }
    __syncthreads();

    // ---- S4: a = mean_h(acc/denom) + root ----
    for (int idx = tid; idx < NN * 16; idx += NT) {
        const int n = idx >> 4, c = idx & 15;
        float sum = 0.f;
#pragma unroll
        for (int hh = 0; hh < 4; hh++)
            sum += s->acc1[n * 64 + hh * 16 + c] / (s->denom1[n * 4 + hh] + 1e-16f);
        s->a[n * 17 + c] = 0.25f * sum + s->root1[idx];
    }
    __syncthreads();

    // ---- S5: g2 agent-only q and root ----
    {
        const int ag = s->agent;
        const float* ar = &s->a[ag * 17];
        for (int u = tid; u < 128; u += NT) {
            float ac = A.g2bq[u];
#pragma unroll
            for (int j = 0; j < 16; j++) ac += A.g2Wq[u * 16 + j] * ar[j];
            s->qa[u] = ac;
        }
        for (int c = tid; c < 32; c += NT) {
            float ac = A.g2bs[c];
#pragma unroll
            for (int j = 0; j < 16; j++) ac += A.g2Ws[c * 16 + j] * ar[j];
            s->roota[c] = ac;
        }
    }
    __syncthreads();

    // ---- S6: g2 edges with dst == agent only (~32 edges), per (edge,head) ----
    {
        const int ag = s->agent;
        const int p0 = s->rowptr[ag];
        const int m = s->rowptr[ag + 1] - p0;
        for (int w = tid; w < m * 4; w += NT) {
            const int pe = w >> 2, hh = w & 3;
            const int pk = s->csr[p0 + pe];
            const int e = pk & 0xFFFF, src = pk >> 16;
            const float* eap = eag + (size_t)e * 8;
            float ear[8];
#pragma unroll
            for (int j = 0; j < 8; j++) ear[j] = eap[j];
            const float* ar = &s->a[src * 17];
            float ev[32];
            float lg = 0.f;
#pragma unroll
            for (int c = 0; c < 32; c++) {
                const int u = hh * 32 + c;
                float evv = 0.f;
#pragma unroll
                for (int j = 0; j < 8; j++) evv += A.g2We[u * 8 + j] * ear[j];
                ev[c] = evv;
                float kk = A.g2bk[u];
#pragma unroll
                for (int j = 0; j < 16; j++) kk += A.g2Wk[u * 16 + j] * ar[j];
                lg += s->qa[u] * (kk + evv);
            }
            const float ex = __expf(lg * 0.17677669529663689f);  // 1/sqrt(32)
            atomicAdd(&s->denom2[hh], ex);
#pragma unroll
            for (int c = 0; c < 32; c++) {
                const int u = hh * 32 + c;
                float vv = A.g2bv[u];
#pragma unroll
                for (int j = 0; j < 16; j++) vv += A.g2Wv[u * 16 + j] * ar[j];
                atomicAdd(&s->acc2[u], ex * (vv + ev[c]));
            }
        }
    }
    __syncthreads();

    // ---- S7: output = relu(mean_h(acc2/denom2) + root) at agent node ----
    for (int c = tid; c < 32; c += NT) {
        float sum = 0.f;
#pragma unroll
        for (int hh = 0; hh < 4; hh++)
            sum += s->acc2[hh * 32 + c] / (s->denom2[hh] + 1e-16f);
        A.out[b * 32 + c] = fmaxf(0.25f * sum + s->roota[c], 0.f);
    }
}

extern "C" void kernel_launch(void* const* d_in, const int* in_sizes, int n_in,
                              void* d_out, int out_size) {
    Args A;
    A.nodes = (const float*)d_in[0];
    A.ei    = (const int*)  d_in[1];
    A.ea    = (const float*)d_in[2];
    A.agent = (const int*)  d_in[3];
    A.emb   = (const float*)d_in[4];
    A.W1 = (const float*)d_in[5];  A.b1 = (const float*)d_in[6];
    A.W2 = (const float*)d_in[7];  A.b2 = (const float*)d_in[8];
    A.W3 = (const float*)d_in[9];  A.b3 = (const float*)d_in[10];
    A.lng = (const float*)d_in[11]; A.lnb = (const float*)d_in[12];
    A.g1Wq = (const float*)d_in[13]; A.g1bq = (const float*)d_in[14];
    A.g1Wk = (const float*)d_in[15]; A.g1bk = (const float*)d_in[16];
    A.g1Wv = (const float*)d_in[17]; A.g1bv = (const float*)d_in[18];
    A.g1We = (const float*)d_in[19];
    A.g1Ws = (const float*)d_in[20]; A.g1bs = (const float*)d_in[21];
    A.g2Wq = (const float*)d_in[22]; A.g2bq = (const float*)d_in[23];
    A.g2Wk = (const float*)d_in[24]; A.g2bk = (const float*)d_in[25];
    A.g2Wv = (const float*)d_in[26]; A.g2bv = (const float*)d_in[27];
    A.g2We = (const float*)d_in[28];
    A.g2Ws = (const float*)d_in[29]; A.g2bs = (const float*)d_in[30];
    A.out = (float*)d_out;

    cudaFuncSetAttribute(gnn_kernel, cudaFuncAttributeMaxDynamicSharedMemorySize,
                         (int)sizeof(SM));
    gnn_kernel<<<BB, NT, sizeof(SM)>>>(A);
}